// round 4
// baseline (speedup 1.0000x reference)
#include <cuda_runtime.h>
#include <cuda_bf16.h>

// out[b, 1+d, p] = x[b, c, hx(p)*16+pi, hy(p)*16+pj] + pos[1+d, p]
//   where d = c*256 + pi*16 + pj, (hx,hy) = hilbert_d2xy(32, p)
// out[b, 0, e]   = cls[e] + pos[0, e]   (fused into ptile==0,dtile==0 CTA)
//
// Vectorized tiled transpose, 2 p-tiles per CTA software-pipelined:
// tile1's LDGs are issued before tile0's store phase so their DRAM latency
// hides behind ~1KB/thread of smem+gmem store work. Single 16KB buffer keeps
// 8 CTAs/SM. All smem traffic is 128-bit, conflict-free (xor swizzle).

__global__ __launch_bounds__(256) void hilbert_main_kernel(
    const float* __restrict__ x,
    const float* __restrict__ cls,
    const float* __restrict__ pos,
    float* __restrict__ out)
{
    __shared__ float4 sm4[128 * 8];    // [d][q], q xor-swizzled
    __shared__ int pbase[64];          // [tile][32 patches]

    const int ptile = blockIdx.x;      // 0..15 (handles ptile and ptile+16)
    const int dtile = blockIdx.y;      // 0..7
    const int b     = blockIdx.z;      // 0..63
    const int tid   = threadIdx.x;

    const int c   = dtile >> 1;        // channel (d-tile of 128 = half a channel)
    const int pi0 = (dtile & 1) * 8;   // starting patch row within channel
    const int d0  = dtile * 128;
    const long out_b = (long)b * (1025L * 1024L);

    // Hilbert d2xy for both tiles' 64 patches (N=32, 5 iterations)
    if (tid < 64) {
        int t = (ptile + (tid >> 5) * 16) * 32 + (tid & 31);
        int hx = 0, hy = 0;
        #pragma unroll
        for (int s = 1; s < 32; s <<= 1) {
            int rx = 1 & (t >> 1);
            int ry = 1 & (t ^ rx);
            if (ry == 0) {
                if (rx == 1) { hx = s - 1 - hx; hy = s - 1 - hy; }
                int tmp = hx; hx = hy; hy = tmp;
            }
            hx += s * rx;
            hy += s * ry;
            t >>= 2;
        }
        pbase[tid] = ((b * 4 + c) * 512 + hx * 16 + pi0) * 512 + hy * 16;
    }

    // Fused row0: out[b, 0, :] = cls + pos[0, :]  (one CTA per batch)
    if (ptile == 0 && dtile == 0) {
        float4 cv = *reinterpret_cast<const float4*>(cls + tid * 4);
        float4 pv = *reinterpret_cast<const float4*>(pos + tid * 4);
        cv.x += pv.x; cv.y += pv.y; cv.z += pv.z; cv.w += pv.w;
        *reinterpret_cast<float4*>(out + out_b + tid * 4) = cv;
    }
    __syncthreads();

    const int f = tid & 31;            // float4 slot within patch slab (d = 4f..4f+3)
    const int q = tid >> 5;            // p-quad 0..7
    const float* src = x + (f >> 2) * 512 + (f & 3) * 4;
    const int base = 32 * f + (q ^ (f & 7));   // d=4f+j at base + 8j

    // ---- Tile 0 load + 4x4 register transpose + STS.128 ----
    {
        const float4 v0 = *reinterpret_cast<const float4*>(src + pbase[4 * q + 0]);
        const float4 v1 = *reinterpret_cast<const float4*>(src + pbase[4 * q + 1]);
        const float4 v2 = *reinterpret_cast<const float4*>(src + pbase[4 * q + 2]);
        const float4 v3 = *reinterpret_cast<const float4*>(src + pbase[4 * q + 3]);
        sm4[base     ] = make_float4(v0.x, v1.x, v2.x, v3.x);
        sm4[base +  8] = make_float4(v0.y, v1.y, v2.y, v3.y);
        sm4[base + 16] = make_float4(v0.z, v1.z, v2.z, v3.z);
        sm4[base + 24] = make_float4(v0.w, v1.w, v2.w, v3.w);
    }
    __syncthreads();

    // ---- Issue tile 1 loads NOW; latency hides behind tile 0 store phase ----
    const float4 w0 = *reinterpret_cast<const float4*>(src + pbase[32 + 4 * q + 0]);
    const float4 w1 = *reinterpret_cast<const float4*>(src + pbase[32 + 4 * q + 1]);
    const float4 w2 = *reinterpret_cast<const float4*>(src + pbase[32 + 4 * q + 2]);
    const float4 w3 = *reinterpret_cast<const float4*>(src + pbase[32 + 4 * q + 3]);

    // ---- Tile 0 store phase: LDS.128 + pos add + STG.128 ----
    {
        const int p0 = ptile * 32;
        #pragma unroll
        for (int k = 0; k < 4; k++) {
            const int idx = k * 256 + tid;
            const int d   = idx >> 3;
            const int qq  = idx & 7;
            float4 r = sm4[d * 8 + (qq ^ ((d >> 2) & 7))];
            const long row = (long)(1 + d0 + d);
            const long col = (long)(p0 + qq * 4);
            const float4 pe = *reinterpret_cast<const float4*>(pos + row * 1024 + col);
            r.x += pe.x; r.y += pe.y; r.z += pe.z; r.w += pe.w;
            __stcs(reinterpret_cast<float4*>(out + out_b + row * 1024 + col), r);
        }
    }
    __syncthreads();

    // ---- Tile 1 STS ----
    sm4[base     ] = make_float4(w0.x, w1.x, w2.x, w3.x);
    sm4[base +  8] = make_float4(w0.y, w1.y, w2.y, w3.y);
    sm4[base + 16] = make_float4(w0.z, w1.z, w2.z, w3.z);
    sm4[base + 24] = make_float4(w0.w, w1.w, w2.w, w3.w);
    __syncthreads();

    // ---- Tile 1 store phase ----
    {
        const int p0 = (ptile + 16) * 32;
        #pragma unroll
        for (int k = 0; k < 4; k++) {
            const int idx = k * 256 + tid;
            const int d   = idx >> 3;
            const int qq  = idx & 7;
            float4 r = sm4[d * 8 + (qq ^ ((d >> 2) & 7))];
            const long row = (long)(1 + d0 + d);
            const long col = (long)(p0 + qq * 4);
            const float4 pe = *reinterpret_cast<const float4*>(pos + row * 1024 + col);
            r.x += pe.x; r.y += pe.y; r.z += pe.z; r.w += pe.w;
            __stcs(reinterpret_cast<float4*>(out + out_b + row * 1024 + col), r);
        }
    }
}

extern "C" void kernel_launch(void* const* d_in, const int* in_sizes, int n_in,
                              void* d_out, int out_size)
{
    // Identify inputs by size (defensive against ordering):
    //   x: 64*4*512*512 = 67108864, cls: 1024, pos: 1025*1024 = 1049600
    const float* x   = nullptr;
    const float* cls = nullptr;
    const float* pos = nullptr;
    for (int i = 0; i < n_in; i++) {
        if (in_sizes[i] == 67108864)     x   = (const float*)d_in[i];
        else if (in_sizes[i] == 1024)    cls = (const float*)d_in[i];
        else if (in_sizes[i] == 1049600) pos = (const float*)d_in[i];
    }
    float* out = (float*)d_out;

    dim3 grid(16, 8, 64);   // p-tile pairs, d-tiles, batch
    hilbert_main_kernel<<<grid, 256>>>(x, cls, pos, out);
}

// round 5
// speedup vs baseline: 1.0262x; 1.0262x over previous
#include <cuda_runtime.h>
#include <cuda_bf16.h>

// out[b, 1+d, p] = x[b, c, hx(p)*16+pi, hy(p)*16+pj] + pos[1+d, p]
//   where d = c*256 + pi*16 + pj, (hx,hy) = hilbert_d2xy(32, p)
// out[b, 0, e]   = cls[e] + pos[0, e]   (fused into ptile==0,dtile==0 CTA)
//
// Smem-free transpose: lane mapping q=lane&7 (p-quad), f=4*warp+(lane>>3)
// (d-quad). Each thread loads a 4(p)x4(d) block (4x LDG.128, 64B/patch-row
// per 8-lane group), transposes in registers, adds pos, and stores 4x STG.128
// where every 8-lane group writes one full 128B output line. No smem, no
// barriers; Hilbert bases per-lane + __shfl_sync.

__global__ __launch_bounds__(256) void hilbert_main_kernel(
    const float* __restrict__ x,
    const float* __restrict__ cls,
    const float* __restrict__ pos,
    float* __restrict__ out)
{
    const int tid = threadIdx.x;
    const int w   = tid >> 5;          // warp 0..7  -> d-quads 4w..4w+3
    const int l   = tid & 31;

    const int ptile = blockIdx.x;      // 0..31
    const int dtile = blockIdx.y;      // 0..7
    const int b     = blockIdx.z;      // 0..63

    const int c   = dtile >> 1;        // channel (d-tile of 128 = half a channel)
    const int pi0 = (dtile & 1) * 8;   // starting patch row within channel
    const int p0  = ptile * 32;
    const int d0  = dtile * 128;
    const long out_b = (long)b * (1025L * 1024L);

    // Per-lane Hilbert d2xy for patch p0+l (N=32, 5 iterations)
    int pb;
    {
        int t = p0 + l;
        int hx = 0, hy = 0;
        #pragma unroll
        for (int s = 1; s < 32; s <<= 1) {
            int rx = 1 & (t >> 1);
            int ry = 1 & (t ^ rx);
            if (ry == 0) {
                if (rx == 1) { hx = s - 1 - hx; hy = s - 1 - hy; }
                int tmp = hx; hx = hy; hy = tmp;
            }
            hx += s * rx;
            hy += s * ry;
            t >>= 2;
        }
        pb = ((b * 4 + c) * 512 + hx * 16 + pi0) * 512 + hy * 16;
    }

    // Fused row0: out[b, 0, :] = cls + pos[0, :]  (one CTA per batch)
    if (ptile == 0 && dtile == 0) {
        float4 cv = *reinterpret_cast<const float4*>(cls + tid * 4);
        float4 pv = *reinterpret_cast<const float4*>(pos + tid * 4);
        cv.x += pv.x; cv.y += pv.y; cv.z += pv.z; cv.w += pv.w;
        *reinterpret_cast<float4*>(out + out_b + tid * 4) = cv;
    }

    const int q = l & 7;               // p-quad: patches 4q..4q+3
    const int s = l >> 3;              // sub-row selector
    // f = 4w + s : float4 slot within patch slab; d = 4f + j
    // x offset of slot f within patch: (f>>2)*512 + (f&3)*4 = w*512 + s*4
    const float* src = x + w * 512 + s * 4;

    const int pb0 = __shfl_sync(0xffffffffu, pb, 4 * q + 0);
    const int pb1 = __shfl_sync(0xffffffffu, pb, 4 * q + 1);
    const int pb2 = __shfl_sync(0xffffffffu, pb, 4 * q + 2);
    const int pb3 = __shfl_sync(0xffffffffu, pb, 4 * q + 3);

    const float4 v0 = *reinterpret_cast<const float4*>(src + pb0);
    const float4 v1 = *reinterpret_cast<const float4*>(src + pb1);
    const float4 v2 = *reinterpret_cast<const float4*>(src + pb2);
    const float4 v3 = *reinterpret_cast<const float4*>(src + pb3);

    // Output rows 1 + d0 + 4f + j, cols p0 + 4q .. +3
    const long row0 = (long)(1 + d0 + 16 * w + 4 * s);
    const float* pp = pos + row0 * 1024 + (p0 + 4 * q);
    float*       op = out + out_b + row0 * 1024 + (p0 + 4 * q);

    const float4 pe0 = *reinterpret_cast<const float4*>(pp);
    const float4 pe1 = *reinterpret_cast<const float4*>(pp + 1024);
    const float4 pe2 = *reinterpret_cast<const float4*>(pp + 2048);
    const float4 pe3 = *reinterpret_cast<const float4*>(pp + 3072);

    float4 r;
    r = make_float4(v0.x + pe0.x, v1.x + pe0.y, v2.x + pe0.z, v3.x + pe0.w);
    __stcs(reinterpret_cast<float4*>(op), r);
    r = make_float4(v0.y + pe1.x, v1.y + pe1.y, v2.y + pe1.z, v3.y + pe1.w);
    __stcs(reinterpret_cast<float4*>(op + 1024), r);
    r = make_float4(v0.z + pe2.x, v1.z + pe2.y, v2.z + pe2.z, v3.z + pe2.w);
    __stcs(reinterpret_cast<float4*>(op + 2048), r);
    r = make_float4(v0.w + pe3.x, v1.w + pe3.y, v2.w + pe3.z, v3.w + pe3.w);
    __stcs(reinterpret_cast<float4*>(op + 3072), r);
}

extern "C" void kernel_launch(void* const* d_in, const int* in_sizes, int n_in,
                              void* d_out, int out_size)
{
    // Identify inputs by size (defensive against ordering):
    //   x: 64*4*512*512 = 67108864, cls: 1024, pos: 1025*1024 = 1049600
    const float* x   = nullptr;
    const float* cls = nullptr;
    const float* pos = nullptr;
    for (int i = 0; i < n_in; i++) {
        if (in_sizes[i] == 67108864)     x   = (const float*)d_in[i];
        else if (in_sizes[i] == 1024)    cls = (const float*)d_in[i];
        else if (in_sizes[i] == 1049600) pos = (const float*)d_in[i];
    }
    float* out = (float*)d_out;

    dim3 grid(32, 8, 64);   // p-tiles, d-tiles, batch
    hilbert_main_kernel<<<grid, 256>>>(x, cls, pos, out);
}